// round 17
// baseline (speedup 1.0000x reference)
#include <cuda_runtime.h>
#include <cuda_fp16.h>
#include <cstdint>

#define SEQ   256
#define BATCH 8192

// pack two f32 -> f16x2 (lo = first arg)
__device__ __forceinline__ uint32_t pkh(float lo, float hi) {
    uint32_t u; asm("cvt.rn.f16x2.f32 %0, %2, %1;" : "=r"(u) : "f"(lo), "f"(hi)); return u;
}
// 8x8 f16 in-warp transpose
__device__ __forceinline__ uint32_t movm(uint32_t s) {
    uint32_t d;
    asm("movmatrix.sync.aligned.m8n8.trans.b16 %0, %1;" : "=r"(d) : "r"(s));
    return d;
}
// D += A*B
__device__ __forceinline__ void mma16(float d[4], const uint32_t a[4],
                                      uint32_t b0, uint32_t b1) {
    asm("mma.sync.aligned.m16n8k16.row.col.f32.f16.f16.f32 "
        "{%0,%1,%2,%3},{%4,%5,%6,%7},{%8,%9},{%0,%1,%2,%3};"
        : "+f"(d[0]), "+f"(d[1]), "+f"(d[2]), "+f"(d[3])
        : "r"(a[0]), "r"(a[1]), "r"(a[2]), "r"(a[3]), "r"(b0), "r"(b1));
}
// D = A*B (fresh accumulator)
__device__ __forceinline__ void mma16o(float d[4], const uint32_t a[4],
                                       uint32_t b0, uint32_t b1) {
    asm("mma.sync.aligned.m16n8k16.row.col.f32.f16.f16.f32 "
        "{%0,%1,%2,%3},{%4,%5,%6,%7},{%8,%9},{%10,%10,%10,%10};"
        : "=f"(d[0]), "=f"(d[1]), "=f"(d[2]), "=f"(d[3])
        : "r"(a[0]), "r"(a[1]), "r"(a[2]), "r"(a[3]), "r"(b0), "r"(b1),
          "f"(0.0f));
}
// f32 gates (proven best): sigmoid(x) = 0.5*tanh(0.5x)+0.5
__device__ __forceinline__ float sig_t(float x) {
    float t; asm("tanh.approx.f32 %0, %1;" : "=f"(t) : "f"(0.5f * x));
    return fmaf(t, 0.5f, 0.5f);
}
__device__ __forceinline__ float tanh_ap(float x) {
    float t; asm("tanh.approx.f32 %0, %1;" : "=f"(t) : "f"(x)); return t;
}

// Grid: 148 blocks x 448 threads (14 warps = 7 pairs).
// Pair P = (wid>>1)*148 + bid, active iff P < 1024; pair owns batch cols
// [8P, 8P+8). Warp s = wid&1 owns hidden units [16s, 16s+16) (one m16 tile).
// Each warp: 18 MMAs, 24 MUFU, 72 weight regs per step — half of R15 —
// and 2048 active warps (3.5/SMSP) double latency hiding.
// Cross-warp h exchange: each warp's 16 units = exactly 2 B-frag words
// (via movmatrix), so exchange = STS.64 + bar.sync(64) + LDS.64 per state.
__global__ void __launch_bounds__(448, 1) gru2_ws_kernel(
    const float* __restrict__ x,
    const float* __restrict__ h_in,
    const float* __restrict__ Wih0,
    const float* __restrict__ Whh0,
    const float* __restrict__ bih0,
    const float* __restrict__ bhh0,
    const float* __restrict__ Wih1,
    const float* __restrict__ Whh1,
    const float* __restrict__ bih1,
    const float* __restrict__ bhh1,
    const float* __restrict__ Wout,
    const float* __restrict__ bout,
    float* __restrict__ out)
{
    __shared__ float4 KA[32];      // (Wih0_r, Wih0_z, Wih0_n, bih0_n)
    __shared__ float4 KB[32];      // (br0c, bz0c, bhn0, Wout)
    __shared__ float4 KC[32];      // (br1c, bz1c, bin1, bhn1)
    __shared__ float  boS;
    __shared__ __align__(8) uint2  hx0[7 * 64];   // [pib][s][lane] B-word pairs
    __shared__ __align__(8) uint2  hx1[7 * 64];
    __shared__ float2 yS[7 * 8];                  // [pib][s][tg] y partials

    const int tid = threadIdx.x;
    if (tid < 32) {
        int u = tid;
        KA[u] = make_float4(Wih0[u], Wih0[32 + u], Wih0[64 + u], bih0[64 + u]);
        KB[u] = make_float4(bih0[u] + bhh0[u], bih0[32 + u] + bhh0[32 + u],
                            bhh0[64 + u], Wout[u]);
        KC[u] = make_float4(bih1[u] + bhh1[u], bih1[32 + u] + bhh1[32 + u],
                            bih1[64 + u], bhh1[64 + u]);
    }
    if (tid == 0) boS = bout[0];
    __syncthreads();

    const int wid  = tid >> 5;
    const int lane = tid & 31;
    const int pib  = wid >> 1;          // pair in block (0..6)
    const int s    = wid & 1;           // hidden-half (m-tile)
    const int P    = pib * 148 + blockIdx.x;
    if (P >= 1024) return;              // 12 idle pairs

    const int g  = lane >> 2;
    const int tg = lane & 3;
    const int base = P * 8;
    const int barId = pib + 1;
    const float bo = boS;

    uint2* myx0 = &hx0[pib * 64 + s * 32 + lane];
    uint2* px0  = &hx0[pib * 64 + (1 - s) * 32 + lane];
    uint2* myx1 = &hx1[pib * 64 + s * 32 + lane];
    uint2* px1  = &hx1[pib * 64 + (1 - s) * 32 + lane];
    const int oB = 2 * s;        // own B-word slot
    const int pB = 2 * (1 - s);  // partner B-word slot

#define BARP() asm volatile("bar.sync %0, 64;" :: "r"(barId) : "memory")

    // ---- weight A-fragments for own m-tile (18 tiles x 4 regs = 72) ----
    uint32_t W0[3][2][4], Wi[3][2][4], Wh[3][2][4];
#pragma unroll
    for (int gate = 0; gate < 3; gate++)
#pragma unroll
        for (int kt = 0; kt < 2; kt++)
#pragma unroll
            for (int aa = 0; aa < 4; aa++) {
                int row = gate * 32 + 16 * s + g + (aa & 1) * 8;
                int col = kt * 16 + 2 * tg + (aa >> 1) * 8;
                float2 v0 = *(const float2*)&Whh0[row * 32 + col];
                float2 vi = *(const float2*)&Wih1[row * 32 + col];
                float2 vh = *(const float2*)&Whh1[row * 32 + col];
                W0[gate][kt][aa] = pkh(v0.x, v0.y);
                Wi[gate][kt][aa] = pkh(vi.x, vi.y);
                Wh[gate][kt][aa] = pkh(vh.x, vh.y);
            }

    // ---- h masters (f32 D-layout, own 16 units): idx rr*2+c ----
    float h0D[4], h1D[4];
#pragma unroll
    for (int rr = 0; rr < 2; rr++)
#pragma unroll
        for (int c = 0; c < 2; c++) {
            int u = 16 * s + 8 * rr + g;
            int b = base + 2 * tg + c;
            h0D[rr * 2 + c] = h_in[(size_t)b * 32 + u];
            h1D[rr * 2 + c] = h_in[(size_t)(BATCH + b) * 32 + u];
        }

    // ---- initial B-fragments: own words via movmatrix, partner via smem ----
    uint32_t hB0[4], hB1[4];
    {
        uint32_t a0 = movm(pkh(h0D[0], h0D[1])), b0w = movm(pkh(h0D[2], h0D[3]));
        uint32_t a1 = movm(pkh(h1D[0], h1D[1])), b1w = movm(pkh(h1D[2], h1D[3]));
        *myx0 = make_uint2(a0, b0w);
        *myx1 = make_uint2(a1, b1w);
        BARP();
        uint2 q0 = *px0, q1 = *px1;
        hB0[oB] = a0;  hB0[oB + 1] = b0w;  hB0[pB] = q0.x;  hB0[pB + 1] = q0.y;
        hB1[oB] = a1;  hB1[oB + 1] = b1w;  hB1[pB] = q1.x;  hB1[pB + 1] = q1.y;
    }

    float2 xv = *(const float2*)&x[base + 2 * tg];

    for (int st = 0; st < SEQ; st++) {
        float2 xn = *(const float2*)&x[(size_t)min(st + 1, SEQ - 1) * BATCH + base + 2 * tg];

        // ---------- L0 MMAs (own 3 gate tiles) ----------
        float Dr[4], Dz[4], Dn[4];
        mma16o(Dr, W0[0][0], hB0[0], hB0[1]);
        mma16 (Dr, W0[0][1], hB0[2], hB0[3]);
        mma16o(Dz, W0[1][0], hB0[0], hB0[1]);
        mma16 (Dz, W0[1][1], hB0[2], hB0[3]);
        mma16o(Dn, W0[2][0], hB0[0], hB0[1]);
        mma16 (Dn, W0[2][1], hB0[2], hB0[3]);

        // ---------- L1 Wh-part MMAs (independent; overlap L0 + bar A) ----------
        float Er[4], Ez[4], Eh[4];
        mma16o(Er, Wh[0][0], hB1[0], hB1[1]);
        mma16 (Er, Wh[0][1], hB1[2], hB1[3]);
        mma16o(Ez, Wh[1][0], hB1[0], hB1[1]);
        mma16 (Ez, Wh[1][1], hB1[2], hB1[3]);
        mma16o(Eh, Wh[2][0], hB1[0], hB1[1]);
        mma16 (Eh, Wh[2][1], hB1[2], hB1[3]);

        // ---------- L0 epilogue (4 instances, f32 gates) ----------
#pragma unroll
        for (int rr = 0; rr < 2; rr++) {
            const int u = 16 * s + 8 * rr + g;
            const float4 A  = KA[u];
            const float4 Bc = KB[u];
#pragma unroll
            for (int c = 0; c < 2; c++) {
                const int di = rr * 2 + c;
                const float xvc = c ? xv.y : xv.x;
                float r = sig_t(fmaf(xvc, A.x, Dr[di] + Bc.x));
                float z = sig_t(fmaf(xvc, A.y, Dz[di] + Bc.y));
                float n = tanh_ap(fmaf(xvc, A.z, A.w) + r * (Dn[di] + Bc.z));
                float hold = h0D[di];
                h0D[di] = n + z * (hold - n);
            }
        }
        // h0' -> own B-words; exchange
        {
            uint32_t a0 = movm(pkh(h0D[0], h0D[1]));
            uint32_t b0w = movm(pkh(h0D[2], h0D[3]));
            *myx0 = make_uint2(a0, b0w);
            BARP();                               // bar A (Wh MMAs in flight)
            uint2 q = *px0;
            hB0[oB] = a0; hB0[oB + 1] = b0w; hB0[pB] = q.x; hB0[pB + 1] = q.y;
        }

        // ---------- L1 Wi-part MMAs ----------
        float Ei[4];
        mma16 (Er, Wi[0][0], hB0[0], hB0[1]);
        mma16 (Er, Wi[0][1], hB0[2], hB0[3]);
        mma16 (Ez, Wi[1][0], hB0[0], hB0[1]);
        mma16 (Ez, Wi[1][1], hB0[2], hB0[3]);
        mma16o(Ei, Wi[2][0], hB0[0], hB0[1]);
        mma16 (Ei, Wi[2][1], hB0[2], hB0[3]);

        // ---------- L1 epilogue + y partials ----------
        float y0 = 0.0f, y1 = 0.0f;
#pragma unroll
        for (int rr = 0; rr < 2; rr++) {
            const int u = 16 * s + 8 * rr + g;
            const float4 C = KC[u];
            const float wou = KB[u].w;
#pragma unroll
            for (int c = 0; c < 2; c++) {
                const int di = rr * 2 + c;
                float r = sig_t(Er[di] + C.x);
                float z = sig_t(Ez[di] + C.y);
                float n = tanh_ap(Ei[di] + C.z + r * (Eh[di] + C.w));
                float hold = h1D[di];
                float hn = n + z * (hold - n);
                h1D[di] = hn;
                if (c) y1 = fmaf(hn, wou, y1); else y0 = fmaf(hn, wou, y0);
            }
        }
        // h1' -> own B-words + y partials; exchange
        {
            uint32_t a1 = movm(pkh(h1D[0], h1D[1]));
            uint32_t b1w = movm(pkh(h1D[2], h1D[3]));
            *myx1 = make_uint2(a1, b1w);
            // y reduce over g lanes (bits 2,3,4)
            y0 += __shfl_xor_sync(0xffffffffu, y0, 4);
            y0 += __shfl_xor_sync(0xffffffffu, y0, 8);
            y0 += __shfl_xor_sync(0xffffffffu, y0, 16);
            y1 += __shfl_xor_sync(0xffffffffu, y1, 4);
            y1 += __shfl_xor_sync(0xffffffffu, y1, 8);
            y1 += __shfl_xor_sync(0xffffffffu, y1, 16);
            if (lane < 4) yS[pib * 8 + s * 4 + tg] = make_float2(y0, y1);
            BARP();                               // bar B
            uint2 q = *px1;
            hB1[oB] = a1; hB1[oB + 1] = b1w; hB1[pB] = q.x; hB1[pB + 1] = q.y;
            if (s == 0 && lane < 4) {
                float2 py = yS[pib * 8 + 4 + tg];
                float2 yo = make_float2(y0 + py.x + bo, y1 + py.y + bo);
                *(float2*)&out[(size_t)st * BATCH + base + 2 * tg] = yo;
            }
        }
        xv = xn;
    }

    // final h_state (2, B, 32): own 16 units
    float* hout = out + (size_t)SEQ * BATCH;
#pragma unroll
    for (int rr = 0; rr < 2; rr++)
#pragma unroll
        for (int c = 0; c < 2; c++) {
            int u = 16 * s + 8 * rr + g;
            int b = base + 2 * tg + c;
            hout[(size_t)b * 32 + u] = h0D[rr * 2 + c];
            hout[(size_t)(BATCH + b) * 32 + u] = h1D[rr * 2 + c];
        }
#undef BARP
}

extern "C" void kernel_launch(void* const* d_in, const int* in_sizes, int n_in,
                              void* d_out, int out_size) {
    (void)in_sizes; (void)n_in; (void)out_size;
    const float* x    = (const float*)d_in[0];
    const float* h    = (const float*)d_in[1];
    const float* Wih0 = (const float*)d_in[2];
    const float* Whh0 = (const float*)d_in[3];
    const float* bih0 = (const float*)d_in[4];
    const float* bhh0 = (const float*)d_in[5];
    const float* Wih1 = (const float*)d_in[6];
    const float* Whh1 = (const float*)d_in[7];
    const float* bih1 = (const float*)d_in[8];
    const float* bhh1 = (const float*)d_in[9];
    const float* Wout = (const float*)d_in[10];
    const float* bout = (const float*)d_in[11];

    // 148 blocks x 14 warps (7 pairs): 2048 active warps, 3.5/SMSP
    gru2_ws_kernel<<<148, 448>>>(x, h, Wih0, Whh0, bih0, bhh0,
                                 Wih1, Whh1, bih1, bhh1, Wout, bout,
                                 (float*)d_out);
}